// round 15
// baseline (speedup 1.0000x reference)
#include <cuda_runtime.h>
#include <cuda_fp16.h>
#include <math_constants.h>
#include <stdint.h>

// SupCon multi-class loss, 2-launch version.
// A: fp32->fp16 convert + class-sum atomics (g_C, g_ccnt).
// Main: fused fp16 HMMA + pure-lse online softmax, then in-kernel completion:
//   per-row-block ticket -> 2nd CTA computes losses (ps = z.C[l] - |z|^2),
//   global ticket -> last CTA writes out[0] and restores all state to zero.

#define TAU_F 0.1f
#define LOG2E_F 1.4426950408889634f
#define LN2_F 0.69314718055994531f
#define SCALE_F (LOG2E_F / TAU_F)

#define BSZ 8192
#define DDIM 128
#define NCLS 128                  // label slots (labels < 100)
#define BM 64
#define BN 128
#define NSPLIT 2
#define COLS_CTA (BSZ / NSPLIT)   // 4096
#define NTILES (COLS_CTA / BN)    // 32
#define NTHR 256
#define NROWBLK (BSZ / BM)        // 128

// SMEM in halves; row stride 136 halves (272B) -> conflict-free ldmatrix.
#define RSTR 136
#define A_HI 0
#define B_OFFH(st) ((64 * RSTR) + ((st) * (128 * RSTR)))
#define SMEM_HALVES (64 * RSTR + 2 * 128 * RSTR)
#define SMEM_BYTES (SMEM_HALVES * 2)   // 87040

__device__ __half  g_zhi[BSZ * DDIM];
__device__ float2  g_part[NSPLIT][BSZ];   // (max, sumexp) per row per col-half
__device__ float   g_C[NCLS * DDIM];      // class sums (zero at entry, restored)
__device__ int     g_ccnt[NCLS];          // class counts (restored)
__device__ int     g_rowTicket[NROWBLK];  // per-row-block arrival (restored)
__device__ int     g_doneCnt;             // finalizer count (restored)
__device__ double  g_sum;                 // (restored)
__device__ int     g_cnt;                 // (restored)

// ---------------- asm helpers ----------------
__device__ __forceinline__ float ex2(float x) {
    float y; asm("ex2.approx.ftz.f32 %0, %1;" : "=f"(y) : "f"(x)); return y;
}
__device__ __forceinline__ void cpa16(uint32_t sa, const void* g) {
    asm volatile("cp.async.cg.shared.global [%0], [%1], 16;" :: "r"(sa), "l"(g));
}
__device__ __forceinline__ void ldsm_x4(uint32_t* r, uint32_t addr) {
    asm volatile("ldmatrix.sync.aligned.m8n8.x4.shared.b16 {%0,%1,%2,%3}, [%4];"
                 : "=r"(r[0]), "=r"(r[1]), "=r"(r[2]), "=r"(r[3]) : "r"(addr));
}
__device__ __forceinline__ void mma16816(float* c, const uint32_t* a,
                                         uint32_t b0, uint32_t b1) {
    asm volatile(
        "mma.sync.aligned.m16n8k16.row.col.f32.f16.f16.f32 "
        "{%0,%1,%2,%3}, {%4,%5,%6,%7}, {%8,%9}, {%0,%1,%2,%3};"
        : "+f"(c[0]), "+f"(c[1]), "+f"(c[2]), "+f"(c[3])
        : "r"(a[0]), "r"(a[1]), "r"(a[2]), "r"(a[3]), "r"(b0), "r"(b1));
}

// ---------------- kernel A: convert + class sums ----------------
__global__ void supcon_convert_kernel(const float* __restrict__ z,
                                      const int* __restrict__ labels) {
    int i = blockIdx.x * blockDim.x + threadIdx.x;   // BSZ*64 float2 elems
    int row = i >> 6, d2 = i & 63;
    float2 f = reinterpret_cast<const float2*>(z)[i];
    reinterpret_cast<__half2*>(g_zhi)[i] = __floats2half2_rn(f.x, f.y);
    int lb = labels[row];
    atomicAdd(&g_C[lb * DDIM + 2 * d2],     f.x);
    atomicAdd(&g_C[lb * DDIM + 2 * d2 + 1], f.y);
    if (d2 == 0) atomicAdd(&g_ccnt[lb], 1);
}

// ---------------- main kernel ----------------
__global__ __launch_bounds__(NTHR, 2)
void supcon_main_kernel(const float* __restrict__ z,
                        const int* __restrict__ labels,
                        float* __restrict__ out) {
    extern __shared__ __half sh[];
    const int tid  = threadIdx.x;
    const int lane = tid & 31;
    const int w    = tid >> 5;
    const int wm   = w & 1;          // 2 warps over M
    const int wn   = w >> 1;         // 4 warps over N
    const int cs      = blockIdx.x;             // column split 0/1
    const int rowBase = blockIdx.y * BM;
    const int colOrig = cs * COLS_CTA;
    // tile index (within this CTA) containing the diagonal, or -1
    const int tdg = (cs == (rowBase >> 12)) ? ((rowBase & 4095) >> 7) : -1;
    const uint32_t sbase = (uint32_t)__cvta_generic_to_shared(sh);

    const uint4* zhi4 = reinterpret_cast<const uint4*>(g_zhi);

    // ---- persistent A tile ----
    #pragma unroll
    for (int it = 0; it < 4; ++it) {
        int idx = tid + it * NTHR;          // 0..1023
        int row = idx >> 4, ch = idx & 15;
        uint4 v = zhi4[(rowBase + row) * 16 + ch];
        *reinterpret_cast<uint4*>(sh + A_HI + row * RSTR + ch * 8) = v;
    }

    // ---- fragment smem addresses ----
    const int arow = lane & 15, akad = (lane >> 4) * 8;
    uint32_t aAddr[2];
    #pragma unroll
    for (int mt = 0; mt < 2; ++mt)
        aAddr[mt] = sbase + (A_HI + (wm * 32 + mt * 16 + arow) * RSTR + akad) * 2;
    const int brow = ((lane >> 4) << 3) + (lane & 7);
    const int bkad = ((lane >> 3) & 1) * 8;
    uint32_t bAddr[2][2];
    #pragma unroll
    for (int st = 0; st < 2; ++st)
        #pragma unroll
        for (int bt = 0; bt < 2; ++bt)
            bAddr[st][bt] = sbase + (B_OFFH(st) +
                            (wn * 32 + bt * 16 + brow) * RSTR + bkad) * 2;

    float acc[2][4][4];
    #pragma unroll
    for (int mt = 0; mt < 2; ++mt)
        #pragma unroll
        for (int nt = 0; nt < 4; ++nt)
            #pragma unroll
            for (int e = 0; e < 4; ++e) acc[mt][nt][e] = 0.f;

    float m[4], s[4];
    #pragma unroll
    for (int r = 0; r < 4; ++r) { m[r] = -CUDART_INF_F; s[r] = 0.f; }

    auto issue_b = [&](int t, int st) {
        #pragma unroll
        for (int it = 0; it < 8; ++it) {
            int idx = tid + it * NTHR;      // 0..2047
            int row = idx >> 4, ch = idx & 15;
            cpa16(sbase + (B_OFFH(st) + row * RSTR + ch * 8) * 2,
                  zhi4 + (colOrig + t * 128 + row) * 16 + ch);
        }
        asm volatile("cp.async.commit_group;" ::: "memory");
    };

    issue_b(0, 0);

    #pragma unroll 1
    for (int t = 0; t < NTILES; ++t) {
        const int st = t & 1;
        if (t + 1 < NTILES) {
            issue_b(t + 1, st ^ 1);
            asm volatile("cp.async.wait_group 1;" ::: "memory");
        } else {
            asm volatile("cp.async.wait_group 0;" ::: "memory");
        }
        __syncthreads();

        // ---- GEMM tile t ----
        #pragma unroll
        for (int kc = 0; kc < 8; ++kc) {
            uint32_t ah[2][4], bh[2][4];
            #pragma unroll
            for (int mt = 0; mt < 2; ++mt) ldsm_x4(ah[mt], aAddr[mt] + kc * 32);
            #pragma unroll
            for (int bt = 0; bt < 2; ++bt) ldsm_x4(bh[bt], bAddr[st][bt] + kc * 32);
            #pragma unroll
            for (int mt = 0; mt < 2; ++mt)
                #pragma unroll
                for (int bt = 0; bt < 2; ++bt) {
                    mma16816(acc[mt][bt * 2],     ah[mt], bh[bt][0], bh[bt][1]);
                    mma16816(acc[mt][bt * 2 + 1], ah[mt], bh[bt][2], bh[bt][3]);
                }
        }

        // ---- pure-lse fold ----
        if (t != tdg) {
            #pragma unroll
            for (int r = 0; r < 4; ++r) {
                const int mt = r >> 1, off = (r & 1) * 2;
                float tv = -CUDART_INF_F;
                #pragma unroll
                for (int nt = 0; nt < 4; ++nt) {
                    tv = fmaxf(tv, acc[mt][nt][off]);
                    tv = fmaxf(tv, acc[mt][nt][off + 1]);
                }
                float mn = fmaxf(m[r], tv * SCALE_F);
                float ss = s[r] * ex2(m[r] - mn);
                float s0 = 0.f, s1 = 0.f;
                #pragma unroll
                for (int nt = 0; nt < 4; ++nt) {
                    s0 += ex2(fmaf(acc[mt][nt][off],     SCALE_F, -mn));
                    s1 += ex2(fmaf(acc[mt][nt][off + 1], SCALE_F, -mn));
                    acc[mt][nt][off] = 0.f;
                    acc[mt][nt][off + 1] = 0.f;
                }
                m[r] = mn; s[r] = ss + s0 + s1;
            }
        } else {
            const int colBase = colOrig + t * BN;
            #pragma unroll
            for (int r = 0; r < 4; ++r) {
                const int mt = r >> 1, off = (r & 1) * 2;
                const int growr = rowBase + wm * 32 + (r >> 1) * 16 + ((r & 1) << 3) + (lane >> 2);
                float vv[8];
                #pragma unroll
                for (int j = 0; j < 8; ++j) {
                    int gcol = colBase + wn * 32 + (j >> 1) * 8 + (lane & 3) * 2 + (j & 1);
                    float v = acc[mt][j >> 1][off + (j & 1)];
                    vv[j] = (gcol == growr) ? -CUDART_INF_F : v;
                    acc[mt][j >> 1][off + (j & 1)] = 0.f;
                }
                float tv = -CUDART_INF_F;
                #pragma unroll
                for (int j = 0; j < 8; ++j) tv = fmaxf(tv, vv[j]);
                float mn = fmaxf(m[r], tv * SCALE_F);
                float ss = s[r] * ex2(m[r] - mn);
                float s0 = 0.f, s1 = 0.f;
                #pragma unroll
                for (int j = 0; j < 8; j += 2) {
                    s0 += ex2(fmaf(vv[j],     SCALE_F, -mn));
                    s1 += ex2(fmaf(vv[j + 1], SCALE_F, -mn));
                }
                m[r] = mn; s[r] = ss + s0 + s1;
            }
        }

        __syncthreads();   // stage reuse guard
    }

    // ---- merge 4 threads (lane&3) sharing each row ----
    #pragma unroll
    for (int r = 0; r < 4; ++r) {
        #pragma unroll
        for (int ox = 1; ox <= 2; ox <<= 1) {
            float mo = __shfl_xor_sync(0xFFFFFFFFu, m[r], ox);
            float so = __shfl_xor_sync(0xFFFFFFFFu, s[r], ox);
            float nm = fmaxf(m[r], mo);
            s[r] = s[r] * ex2(m[r] - nm) + so * ex2(mo - nm);
            m[r] = nm;
        }
    }

    // ---- cross-warp merge over wn ----
    float2* red = reinterpret_cast<float2*>(sh);   // reuse A region (2KB)
    if ((lane & 3) == 0) {
        #pragma unroll
        for (int r = 0; r < 4; ++r) {
            const int lrow = wm * 32 + (r >> 1) * 16 + ((r & 1) << 3) + (lane >> 2);
            red[lrow * 4 + wn] = make_float2(m[r], s[r]);
        }
    }
    __syncthreads();

    if (tid < BM) {
        float2 p0 = red[tid * 4 + 0], p1 = red[tid * 4 + 1];
        float2 p2 = red[tid * 4 + 2], p3 = red[tid * 4 + 3];
        float M = fmaxf(fmaxf(p0.x, p1.x), fmaxf(p2.x, p3.x));
        float S = p0.y * ex2(p0.x - M) + p1.y * ex2(p1.x - M) +
                  p2.y * ex2(p2.x - M) + p3.y * ex2(p3.x - M);
        g_part[cs][rowBase + tid] = make_float2(M, S);
    }

    // ================= in-kernel completion =================
    __shared__ int sIsLast, sIsFin;
    __shared__ float  sLoss[BM];
    __shared__ int    sValid[BM];

    __threadfence();            // publish g_part writes
    __syncthreads();
    if (tid == 0) {
        int old = atomicAdd(&g_rowTicket[blockIdx.y], 1);
        sIsLast = (old == 1);
    }
    __syncthreads();
    if (!sIsLast) return;       // first-arriving CTA of the pair exits

    __threadfence();            // acquire peer CTA's g_part writes

    // 4 threads per row: tid = r*4 + q, dims [q*32, q*32+32)
    {
        const int r = tid >> 2, q = tid & 3;
        const int row = rowBase + r;
        const int l = labels[row];
        const float4* zf4 = reinterpret_cast<const float4*>(z) + row * 32 + q * 8;
        const float4* cf4 = reinterpret_cast<const float4*>(g_C + l * DDIM) + q * 8;
        float ps = 0.f, nrm = 0.f;
        #pragma unroll
        for (int k = 0; k < 8; ++k) {
            float4 zv = zf4[k], cv = cf4[k];
            ps  += zv.x * cv.x + zv.y * cv.y + zv.z * cv.z + zv.w * cv.w;
            nrm += zv.x * zv.x + zv.y * zv.y + zv.z * zv.z + zv.w * zv.w;
        }
        #pragma unroll
        for (int ox = 1; ox <= 2; ox <<= 1) {
            ps  += __shfl_xor_sync(0xFFFFFFFFu, ps,  ox);
            nrm += __shfl_xor_sync(0xFFFFFFFFu, nrm, ox);
        }
        if (q == 0) {
            float loss = 0.f; int valid = 0;
            float2 p0 = g_part[0][row], p1 = g_part[1][row];
            float M = fmaxf(p0.x, p1.x);
            float S = p0.y * ex2(p0.x - M) + p1.y * ex2(p1.x - M);
            int pc = g_ccnt[l] - 1;
            if (pc > 0) {
                float lse = LN2_F * (M + log2f(S));       // natural-log lse
                loss = lse - (ps - nrm) / (TAU_F * (float)pc);
                valid = 1;
            }
            sLoss[r] = loss; sValid[r] = valid;
        }
    }
    __syncthreads();

    if (tid == 0) {
        double bs = 0.0; int bc = 0;
        #pragma unroll
        for (int k = 0; k < BM; ++k) { bs += (double)sLoss[k]; bc += sValid[k]; }
        atomicAdd(&g_sum, bs);
        atomicAdd(&g_cnt, bc);
        g_rowTicket[blockIdx.y] = 0;      // restore for next call
        __threadfence();
        int o2 = atomicAdd(&g_doneCnt, 1);
        sIsFin = (o2 == NROWBLK - 1);
    }
    __syncthreads();
    if (!sIsFin) return;

    __threadfence();            // acquire all finalizers' g_sum/g_cnt atomics
    // restore class state for next call
    for (int i = tid; i < NCLS * DDIM; i += NTHR) g_C[i] = 0.f;
    if (tid < NCLS) g_ccnt[tid] = 0;
    __syncthreads();
    if (tid == 0) {
        int c = g_cnt; if (c < 1) c = 1;
        out[0] = (float)(g_sum / (double)c);
        g_sum = 0.0; g_cnt = 0; g_doneCnt = 0;
        __threadfence();
    }
}

extern "C" void kernel_launch(void* const* d_in, const int* in_sizes, int n_in,
                              void* d_out, int out_size) {
    const float* z      = (const float*)d_in[0];
    const int*   labels = (const int*)d_in[1];
    float*       out    = (float*)d_out;

    static bool attr_set = false;
    if (!attr_set) {
        cudaFuncSetAttribute(supcon_main_kernel,
                             cudaFuncAttributeMaxDynamicSharedMemorySize,
                             SMEM_BYTES);
        attr_set = true;
    }

    supcon_convert_kernel<<<(BSZ * DDIM / 2) / 256, 256>>>(z, labels);
    supcon_main_kernel<<<dim3(NSPLIT, BSZ / BM), NTHR, SMEM_BYTES>>>(z, labels, out);
}

// round 16
// speedup vs baseline: 1.2318x; 1.2318x over previous
#include <cuda_runtime.h>
#include <cuda_fp16.h>
#include <math_constants.h>
#include <stdint.h>

// SupCon multi-class loss: fused fp16 HMMA + pure-lse online softmax.
// Warp-pair-decoupled pipeline: each warp pair (wm0/wm1, same wn) owns its
// 32-col B chunk, loads it with its own cp.async groups, and syncs with
// 2-warp named barriers only -> no CTA-wide barrier in the tile loop.
// pos_sum via class sums: ps_i = z_i . C[l_i] - |z_i|^2 (exact fp32).

#define TAU_F 0.1f
#define LOG2E_F 1.4426950408889634f
#define LN2_F 0.69314718055994531f
#define SCALE_F (LOG2E_F / TAU_F)

#define BSZ 8192
#define DDIM 128
#define NCLS 128
#define BM 64
#define BN 128
#define NSPLIT 2
#define COLS_CTA (BSZ / NSPLIT)   // 4096
#define NTILES (COLS_CTA / BN)    // 32
#define NTHR 256
#define NPOSBLK 256

// SMEM in halves; row stride 136 halves (272B) -> conflict-free ldmatrix.
#define RSTR 136
#define A_HI 0
#define B_OFFH(st) ((64 * RSTR) + ((st) * (128 * RSTR)))
#define SMEM_HALVES (64 * RSTR + 2 * 128 * RSTR)
#define SMEM_BYTES (SMEM_HALVES * 2)   // 87040

__device__ __half  g_zhi[BSZ * DDIM];
__device__ float2  g_part[NSPLIT][BSZ];   // (max, sumexp) per row per col-half
__device__ float   g_C[NCLS * DDIM];      // class sums
__device__ int     g_ccnt[NCLS];          // class counts
__device__ int     g_posDone;             // pos-kernel ticket
__device__ double  g_sum;
__device__ int     g_cnt;

// ---------------- asm helpers ----------------
__device__ __forceinline__ float ex2(float x) {
    float y; asm("ex2.approx.ftz.f32 %0, %1;" : "=f"(y) : "f"(x)); return y;
}
__device__ __forceinline__ void cpa16(uint32_t sa, const void* g) {
    asm volatile("cp.async.cg.shared.global [%0], [%1], 16;" :: "r"(sa), "l"(g));
}
__device__ __forceinline__ void ldsm_x4(uint32_t* r, uint32_t addr) {
    asm volatile("ldmatrix.sync.aligned.m8n8.x4.shared.b16 {%0,%1,%2,%3}, [%4];"
                 : "=r"(r[0]), "=r"(r[1]), "=r"(r[2]), "=r"(r[3]) : "r"(addr));
}
__device__ __forceinline__ void mma16816(float* c, const uint32_t* a,
                                         uint32_t b0, uint32_t b1) {
    asm volatile(
        "mma.sync.aligned.m16n8k16.row.col.f32.f16.f16.f32 "
        "{%0,%1,%2,%3}, {%4,%5,%6,%7}, {%8,%9}, {%0,%1,%2,%3};"
        : "+f"(c[0]), "+f"(c[1]), "+f"(c[2]), "+f"(c[3])
        : "r"(a[0]), "r"(a[1]), "r"(a[2]), "r"(a[3]), "r"(b0), "r"(b1));
}
#define BARP(id) asm volatile("bar.sync %0, 64;" :: "r"(id) : "memory")

// ---------------- kernels ----------------
__global__ void supcon_zero_kernel() {
    int i = blockIdx.x * blockDim.x + threadIdx.x;
    if (i < NCLS * DDIM) g_C[i] = 0.f;
    if (i < NCLS) g_ccnt[i] = 0;
    if (i == 0) { g_sum = 0.0; g_cnt = 0; g_posDone = 0; }
}

__global__ void supcon_convert_kernel(const float* __restrict__ z,
                                      const int* __restrict__ labels) {
    int i = blockIdx.x * blockDim.x + threadIdx.x;   // BSZ*64 float2 elems
    int row = i >> 6, d2 = i & 63;
    float2 f = reinterpret_cast<const float2*>(z)[i];
    reinterpret_cast<__half2*>(g_zhi)[i] = __floats2half2_rn(f.x, f.y);
    int lb = labels[row];
    atomicAdd(&g_C[lb * DDIM + 2 * d2],     f.x);
    atomicAdd(&g_C[lb * DDIM + 2 * d2 + 1], f.y);
    if (d2 == 0) atomicAdd(&g_ccnt[lb], 1);
}

__global__ __launch_bounds__(NTHR, 2)
void supcon_main_kernel() {
    extern __shared__ __half sh[];
    const int tid  = threadIdx.x;
    const int lane = tid & 31;
    const int w    = tid >> 5;
    const int wm   = w & 1;          // 2 warps over M
    const int wn   = w >> 1;         // 4 warps over N; pair = {wm0, wm1} @ wn
    const int barid = wn + 1;        // named barrier per pair (0 = CTA-wide)
    const int cs      = blockIdx.x;             // column split 0/1
    const int rowBase = blockIdx.y * BM;
    const int colOrig = cs * COLS_CTA;
    const int tdg = (cs == (rowBase >> 12)) ? ((rowBase & 4095) >> 7) : -1;
    const uint32_t sbase = (uint32_t)__cvta_generic_to_shared(sh);

    const uint4* zhi4 = reinterpret_cast<const uint4*>(g_zhi);

    // ---- persistent A tile (plain loads) ----
    #pragma unroll
    for (int it = 0; it < 4; ++it) {
        int idx = tid + it * NTHR;          // 0..1023
        int row = idx >> 4, ch = idx & 15;
        uint4 v = zhi4[(rowBase + row) * 16 + ch];
        *reinterpret_cast<uint4*>(sh + A_HI + row * RSTR + ch * 8) = v;
    }

    // ---- per-pair B chunk producer: 32 cols x 128d fp16 = 8KB/stage ----
    // pair-thread id 0..63; 512 uint4 per chunk -> 8 per thread
    const int ptid = wm * 32 + lane;
    auto issue_chunk = [&](int t, int st) {
        #pragma unroll
        for (int it = 0; it < 8; ++it) {
            int idx = ptid + it * 64;       // 0..511
            int row = idx >> 4, ch = idx & 15;
            cpa16(sbase + (B_OFFH(st) + (wn * 32 + row) * RSTR + ch * 8) * 2,
                  zhi4 + (colOrig + t * 128 + wn * 32 + row) * 16 + ch);
        }
        asm volatile("cp.async.commit_group;" ::: "memory");
    };

    issue_chunk(0, 0);
    asm volatile("cp.async.wait_group 0;" ::: "memory");
    __syncthreads();   // A visible to all; chunk0 visible pair-wide

    // ---- fragment smem addresses ----
    const int arow = lane & 15, akad = (lane >> 4) * 8;
    uint32_t aAddr[2];
    #pragma unroll
    for (int mt = 0; mt < 2; ++mt)
        aAddr[mt] = sbase + (A_HI + (wm * 32 + mt * 16 + arow) * RSTR + akad) * 2;
    const int brow = ((lane >> 4) << 3) + (lane & 7);
    const int bkad = ((lane >> 3) & 1) * 8;
    uint32_t bAddr[2][2];
    #pragma unroll
    for (int st = 0; st < 2; ++st)
        #pragma unroll
        for (int bt = 0; bt < 2; ++bt)
            bAddr[st][bt] = sbase + (B_OFFH(st) +
                            (wn * 32 + bt * 16 + brow) * RSTR + bkad) * 2;

    float acc[2][4][4];
    #pragma unroll
    for (int mt = 0; mt < 2; ++mt)
        #pragma unroll
        for (int nt = 0; nt < 4; ++nt)
            #pragma unroll
            for (int e = 0; e < 4; ++e) acc[mt][nt][e] = 0.f;

    float m[4], s[4];
    #pragma unroll
    for (int r = 0; r < 4; ++r) { m[r] = -CUDART_INF_F; s[r] = 0.f; }

    #pragma unroll 1
    for (int t = 0; t < NTILES; ++t) {
        const int st = t & 1;
        if (t + 1 < NTILES) {
            issue_chunk(t + 1, st ^ 1);
            asm volatile("cp.async.wait_group 1;" ::: "memory");
        } else {
            asm volatile("cp.async.wait_group 0;" ::: "memory");
        }
        BARP(barid);   // pair: chunk t data visible from both warps

        // ---- GEMM tile t (this pair's 32 cols) ----
        #pragma unroll
        for (int kc = 0; kc < 8; ++kc) {
            uint32_t ah[2][4], bh[2][4];
            #pragma unroll
            for (int mt = 0; mt < 2; ++mt) ldsm_x4(ah[mt], aAddr[mt] + kc * 32);
            #pragma unroll
            for (int bt = 0; bt < 2; ++bt) ldsm_x4(bh[bt], bAddr[st][bt] + kc * 32);
            #pragma unroll
            for (int mt = 0; mt < 2; ++mt)
                #pragma unroll
                for (int bt = 0; bt < 2; ++bt) {
                    mma16816(acc[mt][bt * 2],     ah[mt], bh[bt][0], bh[bt][1]);
                    mma16816(acc[mt][bt * 2 + 1], ah[mt], bh[bt][2], bh[bt][3]);
                }
        }

        // ---- pure-lse fold (registers only) ----
        if (t != tdg) {
            #pragma unroll
            for (int r = 0; r < 4; ++r) {
                const int mt = r >> 1, off = (r & 1) * 2;
                float tv = -CUDART_INF_F;
                #pragma unroll
                for (int nt = 0; nt < 4; ++nt) {
                    tv = fmaxf(tv, acc[mt][nt][off]);
                    tv = fmaxf(tv, acc[mt][nt][off + 1]);
                }
                float mn = fmaxf(m[r], tv * SCALE_F);
                float ss = s[r] * ex2(m[r] - mn);
                float s0 = 0.f, s1 = 0.f;
                #pragma unroll
                for (int nt = 0; nt < 4; ++nt) {
                    s0 += ex2(fmaf(acc[mt][nt][off],     SCALE_F, -mn));
                    s1 += ex2(fmaf(acc[mt][nt][off + 1], SCALE_F, -mn));
                    acc[mt][nt][off] = 0.f;
                    acc[mt][nt][off + 1] = 0.f;
                }
                m[r] = mn; s[r] = ss + s0 + s1;
            }
        } else {
            const int colBase = colOrig + t * BN;
            #pragma unroll
            for (int r = 0; r < 4; ++r) {
                const int mt = r >> 1, off = (r & 1) * 2;
                const int growr = rowBase + wm * 32 + (r >> 1) * 16 + ((r & 1) << 3) + (lane >> 2);
                float vv[8];
                #pragma unroll
                for (int j = 0; j < 8; ++j) {
                    int gcol = colBase + wn * 32 + (j >> 1) * 8 + (lane & 3) * 2 + (j & 1);
                    float v = acc[mt][j >> 1][off + (j & 1)];
                    vv[j] = (gcol == growr) ? -CUDART_INF_F : v;
                    acc[mt][j >> 1][off + (j & 1)] = 0.f;
                }
                float tv = -CUDART_INF_F;
                #pragma unroll
                for (int j = 0; j < 8; ++j) tv = fmaxf(tv, vv[j]);
                float mn = fmaxf(m[r], tv * SCALE_F);
                float ss = s[r] * ex2(m[r] - mn);
                float s0 = 0.f, s1 = 0.f;
                #pragma unroll
                for (int j = 0; j < 8; j += 2) {
                    s0 += ex2(fmaf(vv[j],     SCALE_F, -mn));
                    s1 += ex2(fmaf(vv[j + 1], SCALE_F, -mn));
                }
                m[r] = mn; s[r] = ss + s0 + s1;
            }
        }

        BARP(barid);   // pair: both warps done reading stage st -> reusable
    }

    // ---- merge 4 threads (lane&3) sharing each row ----
    #pragma unroll
    for (int r = 0; r < 4; ++r) {
        #pragma unroll
        for (int ox = 1; ox <= 2; ox <<= 1) {
            float mo = __shfl_xor_sync(0xFFFFFFFFu, m[r], ox);
            float so = __shfl_xor_sync(0xFFFFFFFFu, s[r], ox);
            float nm = fmaxf(m[r], mo);
            s[r] = s[r] * ex2(m[r] - nm) + so * ex2(mo - nm);
            m[r] = nm;
        }
    }

    // ---- cross-warp merge over wn (CTA-wide) ----
    float2* red = reinterpret_cast<float2*>(sh);   // reuse A region (2KB)
    __syncthreads();   // all pairs done with their loops (A region now free)
    if ((lane & 3) == 0) {
        #pragma unroll
        for (int r = 0; r < 4; ++r) {
            const int lrow = wm * 32 + (r >> 1) * 16 + ((r & 1) << 3) + (lane >> 2);
            red[lrow * 4 + wn] = make_float2(m[r], s[r]);
        }
    }
    __syncthreads();

    if (tid < BM) {
        float2 p0 = red[tid * 4 + 0], p1 = red[tid * 4 + 1];
        float2 p2 = red[tid * 4 + 2], p3 = red[tid * 4 + 3];
        float M = fmaxf(fmaxf(p0.x, p1.x), fmaxf(p2.x, p3.x));
        float S = p0.y * ex2(p0.x - M) + p1.y * ex2(p1.x - M) +
                  p2.y * ex2(p2.x - M) + p3.y * ex2(p3.x - M);
        g_part[cs][rowBase + tid] = make_float2(M, S);
    }
}

// per-row loss (ps = z.C[l] - |z|^2, exact fp32) + in-kernel final via ticket
__global__ __launch_bounds__(1024, 1)
void supcon_pos_kernel(const float* __restrict__ z,
                       const int* __restrict__ labels,
                       float* __restrict__ out) {
    const int lane = threadIdx.x & 31;
    const int wrp  = threadIdx.x >> 5;                // 0..31
    const int row  = blockIdx.x * 32 + wrp;
    const int l = labels[row];
    float4 zv = reinterpret_cast<const float4*>(z)[row * 32 + lane];
    float4 cv = reinterpret_cast<const float4*>(g_C + l * DDIM)[lane];
    float ps  = zv.x * cv.x + zv.y * cv.y + zv.z * cv.z + zv.w * cv.w;
    float nrm = zv.x * zv.x + zv.y * zv.y + zv.z * zv.z + zv.w * zv.w;
    #pragma unroll
    for (int o = 16; o; o >>= 1) {
        ps  += __shfl_down_sync(0xFFFFFFFFu, ps,  o);
        nrm += __shfl_down_sync(0xFFFFFFFFu, nrm, o);
    }
    __shared__ float ls[32];
    __shared__ int   lv[32];
    __shared__ int   sIsLast;
    if (lane == 0) {
        float loss = 0.f; int valid = 0;
        float2 p0 = g_part[0][row], p1 = g_part[1][row];
        float M = fmaxf(p0.x, p1.x);
        float S = p0.y * ex2(p0.x - M) + p1.y * ex2(p1.x - M);
        int pc = g_ccnt[l] - 1;
        if (pc > 0) {
            float lse = LN2_F * (M + log2f(S));           // natural-log lse
            loss = lse - (ps - nrm) / (TAU_F * (float)pc);
            valid = 1;
        }
        ls[wrp] = loss; lv[wrp] = valid;
    }
    __syncthreads();
    if (threadIdx.x == 0) {
        double bs = 0.0; int bc = 0;
        #pragma unroll
        for (int k = 0; k < 32; ++k) { bs += (double)ls[k]; bc += lv[k]; }
        atomicAdd(&g_sum, bs);
        atomicAdd(&g_cnt, bc);
        __threadfence();
        int old = atomicAdd(&g_posDone, 1);
        sIsLast = (old == NPOSBLK - 1);
    }
    __syncthreads();
    if (sIsLast && threadIdx.x == 0) {
        double S = atomicAdd(&g_sum, 0.0);      // coherent reads post-fence
        int    C = atomicAdd(&g_cnt, 0);
        if (C < 1) C = 1;
        out[0] = (float)(S / (double)C);
    }
}

extern "C" void kernel_launch(void* const* d_in, const int* in_sizes, int n_in,
                              void* d_out, int out_size) {
    const float* z      = (const float*)d_in[0];
    const int*   labels = (const int*)d_in[1];
    float*       out    = (float*)d_out;

    static bool attr_set = false;
    if (!attr_set) {
        cudaFuncSetAttribute(supcon_main_kernel,
                             cudaFuncAttributeMaxDynamicSharedMemorySize,
                             SMEM_BYTES);
        attr_set = true;
    }

    supcon_zero_kernel<<<16, 1024>>>();
    supcon_convert_kernel<<<(BSZ * DDIM / 2) / 256, 256>>>(z, labels);
    supcon_main_kernel<<<dim3(NSPLIT, BSZ / BM), NTHR, SMEM_BYTES>>>();
    supcon_pos_kernel<<<BSZ / 32, 1024>>>(z, labels, out);
}